// round 16
// baseline (speedup 1.0000x reference)
#include <cuda_runtime.h>
#include <cuda_fp16.h>
#include <cstdint>

static constexpr int Bx = 4096;
static constexpr int D  = 512;
static constexpr int N  = 8192;
static constexpr float EPS = 1e-8f;

static constexpr int TM = 128;         // tile rows
static constexpr int TN = 256;         // tile cols
static constexpr int BK = 64;          // k-chunk: 64 fp16 = 128B rows
static constexpr int NCH = D / BK;     // 8
static constexpr int NTILE = 1056;     // sum_{I=0}^{63} (I/2 + 1)

static constexpr int STAGE_BYTES = (TM + TN) * BK * 2;   // 49152
static constexpr int SMEM_TOTAL  = 2 * STAGE_BYTES;      // 98304

// scratch (device globals — no allocation allowed)
__device__ __align__(256) __half g_Zh[(size_t)N * D];  // normalized fp16 reps
__device__ float g_pos[Bx];
__device__ float g_rowsum[N];
__device__ int   g_tile;       // tile queue  (reset by last CTA each run)
__device__ int   g_prep_done;  // prep barrier counter
__device__ int   g_done;       // completion ticket

__device__ __forceinline__ void ldmatrix_x4(uint32_t* r, uint32_t addr) {
    asm volatile(
        "ldmatrix.sync.aligned.m8n8.x4.shared.b16 {%0, %1, %2, %3}, [%4];"
        : "=r"(r[0]), "=r"(r[1]), "=r"(r[2]), "=r"(r[3]) : "r"(addr));
}

__device__ __forceinline__ void mma16816h(uint32_t* d, const uint32_t* a,
                                          const uint32_t* b) {
    asm volatile(
        "mma.sync.aligned.m16n8k16.row.col.f16.f16.f16.f16 "
        "{%0, %1}, {%2, %3, %4, %5}, {%6, %7}, {%0, %1};"
        : "+r"(d[0]), "+r"(d[1])
        : "r"(a[0]), "r"(a[1]), "r"(a[2]), "r"(a[3]), "r"(b[0]), "r"(b[1]));
}

__device__ __forceinline__ float exp2dot(float dot) {
    // exp(2*dot) = (poly6(dot/4))^8, |dot/4| <= ~0.26 -> Taylor err ~1e-8
    float r = dot * 0.25f;
    float p = 1.0f / 720.0f;
    p = fmaf(p, r, 1.0f / 120.0f);
    p = fmaf(p, r, 1.0f / 24.0f);
    p = fmaf(p, r, 1.0f / 6.0f);
    p = fmaf(p, r, 0.5f);
    p = fmaf(p, r, 1.0f);
    p = fmaf(p, r, 1.0f);
    p = p * p; p = p * p; p = p * p;
    return p;
}

// ---------------------------------------------------------------------------
// ONE persistent fused kernel: prep -> device barrier -> tile loop -> finalize
// grid = 2 * numSMs (all CTAs resident: 98KB smem + <=128 regs => 2 CTAs/SM)
// ---------------------------------------------------------------------------
__global__ void __launch_bounds__(256, 2) fused_kernel(
        const float* __restrict__ zis, const float* __restrict__ zjs,
        float* __restrict__ out, int G) {
    extern __shared__ __align__(1024) char dynsmem[];
    const uint32_t smem_base = (uint32_t)__cvta_generic_to_shared(dynsmem);
    __shared__ int s_next;
    const int tid = threadIdx.x;
    const int wid = tid >> 5, lid = tid & 31;

    // ================= Phase 1: prep (2 pairs per warp) ====================
    {
        const int gw = blockIdx.x * 8 + wid;    // global warp id
        const int p0 = gw * 2, p1 = gw * 2 + 1;
        if (p0 < Bx) {
            const float4* pa0 = reinterpret_cast<const float4*>(zis + (size_t)p0 * D);
            const float4* pb0 = reinterpret_cast<const float4*>(zjs + (size_t)p0 * D);
            const float4* pa1 = reinterpret_cast<const float4*>(zis + (size_t)p1 * D);
            const float4* pb1 = reinterpret_cast<const float4*>(zjs + (size_t)p1 * D);
            float4 a0[4], b0[4], a1[4], b1[4];
#pragma unroll
            for (int q = 0; q < 4; ++q) a0[q] = pa0[q * 32 + lid];
#pragma unroll
            for (int q = 0; q < 4; ++q) b0[q] = pb0[q * 32 + lid];
#pragma unroll
            for (int q = 0; q < 4; ++q) a1[q] = pa1[q * 32 + lid];
#pragma unroll
            for (int q = 0; q < 4; ++q) b1[q] = pb1[q * 32 + lid];

            float sa0 = 0.f, sb0 = 0.f, dd0 = 0.f, sa1 = 0.f, sb1 = 0.f, dd1 = 0.f;
#pragma unroll
            for (int q = 0; q < 4; ++q) {
                sa0 = fmaf(a0[q].x, a0[q].x, fmaf(a0[q].y, a0[q].y,
                      fmaf(a0[q].z, a0[q].z, fmaf(a0[q].w, a0[q].w, sa0))));
                sb0 = fmaf(b0[q].x, b0[q].x, fmaf(b0[q].y, b0[q].y,
                      fmaf(b0[q].z, b0[q].z, fmaf(b0[q].w, b0[q].w, sb0))));
                dd0 = fmaf(a0[q].x, b0[q].x, fmaf(a0[q].y, b0[q].y,
                      fmaf(a0[q].z, b0[q].z, fmaf(a0[q].w, b0[q].w, dd0))));
                sa1 = fmaf(a1[q].x, a1[q].x, fmaf(a1[q].y, a1[q].y,
                      fmaf(a1[q].z, a1[q].z, fmaf(a1[q].w, a1[q].w, sa1))));
                sb1 = fmaf(b1[q].x, b1[q].x, fmaf(b1[q].y, b1[q].y,
                      fmaf(b1[q].z, b1[q].z, fmaf(b1[q].w, b1[q].w, sb1))));
                dd1 = fmaf(a1[q].x, b1[q].x, fmaf(a1[q].y, b1[q].y,
                      fmaf(a1[q].z, b1[q].z, fmaf(a1[q].w, b1[q].w, dd1))));
            }
#pragma unroll
            for (int o = 16; o > 0; o >>= 1) {
                sa0 += __shfl_xor_sync(0xffffffffu, sa0, o);
                sb0 += __shfl_xor_sync(0xffffffffu, sb0, o);
                dd0 += __shfl_xor_sync(0xffffffffu, dd0, o);
                sa1 += __shfl_xor_sync(0xffffffffu, sa1, o);
                sb1 += __shfl_xor_sync(0xffffffffu, sb1, o);
                dd1 += __shfl_xor_sync(0xffffffffu, dd1, o);
            }
            const float na0 = fmaxf(sqrtf(sa0), EPS), nb0 = fmaxf(sqrtf(sb0), EPS);
            const float na1 = fmaxf(sqrtf(sa1), EPS), nb1 = fmaxf(sqrtf(sb1), EPS);
            if (lid == 0) {
                g_pos[p0] = dd0 / (na0 * nb0) * 2.0f;   // 1/TEMP = 2
                g_pos[p1] = dd1 / (na1 * nb1) * 2.0f;
                g_rowsum[p0] = 0.0f; g_rowsum[Bx + p0] = 0.0f;
                g_rowsum[p1] = 0.0f; g_rowsum[Bx + p1] = 0.0f;
            }
            const float ia0 = 1.0f / na0, ib0 = 1.0f / nb0;
            const float ia1 = 1.0f / na1, ib1 = 1.0f / nb1;
            auto store_row = [&](__half* dst, const float4* v, float sc) {
                uint2* row = reinterpret_cast<uint2*>(dst);
#pragma unroll
                for (int q = 0; q < 4; ++q) {
                    __half2 h0 = __floats2half2_rn(v[q].x * sc, v[q].y * sc);
                    __half2 h1 = __floats2half2_rn(v[q].z * sc, v[q].w * sc);
                    uint2 st;
                    st.x = *reinterpret_cast<uint32_t*>(&h0);
                    st.y = *reinterpret_cast<uint32_t*>(&h1);
                    row[q * 32 + lid] = st;
                }
            };
            store_row(&g_Zh[(size_t)p0 * D], b0, ib0);         // row p = zjs_p
            store_row(&g_Zh[(size_t)(Bx + p0) * D], a0, ia0);  // row Bx+p = zis_p
            store_row(&g_Zh[(size_t)p1 * D], b1, ib1);
            store_row(&g_Zh[(size_t)(Bx + p1) * D], a1, ia1);
        }
    }

    // ============== device-wide barrier (all G CTAs resident) ==============
    __syncthreads();
    if (tid == 0) {
        __threadfence();
        atomicAdd(&g_prep_done, 1);
        while (*(volatile int*)&g_prep_done < G) { __nanosleep(64); }
    }
    __syncthreads();

    // ================= Phase 2: persistent tile loop =======================
    const int wm = wid & 1;        // 2 warps along M (64 rows each)
    const int wn = wid >> 1;       // 4 warps along N (64 cols each)

    auto decode_tile = [](int t, int& rowB, int& colB, bool& str) {
        int s = (int)sqrtf((float)t);
        while ((s + 1) * (s + 1) <= t) ++s;
        while (s * s > t) --s;
        int I, J;
        if (t < s * s + s) { I = 2 * s - 1; J = t - s * s; }
        else               { I = 2 * s;     J = t - s * s - s; }
        rowB = I * TM; colB = J * TN; str = (J == (I >> 1));
    };

    auto load_stage = [&](int stage, int rowBase, int colBase, int c) {
        const uint32_t Ab = smem_base + stage * STAGE_BYTES;
        const uint32_t Bb = Ab + TM * BK * 2;
        const int k0 = c * BK;
#pragma unroll
        for (int it = 0; it < 4; ++it) {       // A: 128 rows * 8 chunks
            int idx = tid + it * 256;
            int r = idx >> 3, seg = idx & 7;
            const __half* src = &g_Zh[(size_t)(rowBase + r) * D + k0 + seg * 8];
            uint32_t dst = Ab + r * 128 + ((seg ^ (r & 7)) << 4);
            asm volatile("cp.async.cg.shared.global [%0], [%1], 16;"
                         :: "r"(dst), "l"(src));
        }
#pragma unroll
        for (int it = 0; it < 8; ++it) {       // B: 256 rows * 8 chunks
            int idx = tid + it * 256;
            int r = idx >> 3, seg = idx & 7;
            const __half* src = &g_Zh[(size_t)(colBase + r) * D + k0 + seg * 8];
            uint32_t dst = Bb + r * 128 + ((seg ^ (r & 7)) << 4);
            asm volatile("cp.async.cg.shared.global [%0], [%1], 16;"
                         :: "r"(dst), "l"(src));
        }
        asm volatile("cp.async.commit_group;");
    };

    uint32_t acc[4][8][2];   // f16x2 accumulators: 4 m-frags x 8 n-frags

    auto compute_stage = [&](int stage) {
        const uint32_t Ab = smem_base + stage * STAGE_BYTES;
        const uint32_t Bb = Ab + TM * BK * 2;
#pragma unroll
        for (int ks = 0; ks < 4; ++ks) {
            const int k0 = ks * 16;  // fp16 index
            uint32_t a[4][4];
#pragma unroll
            for (int mi = 0; mi < 4; ++mi) {
                int row = wm * 64 + mi * 16 + (lid & 7) + ((lid >> 3) & 1) * 8;
                int kch = (k0 + (lid >> 4) * 8) >> 3;
                uint32_t addr = Ab + row * 128 + (((kch ^ (row & 7))) << 4);
                ldmatrix_x4(a[mi], addr);
            }
#pragma unroll
            for (int np = 0; np < 4; ++np) {   // 4 x 16-col B fragments
                int row = wn * 64 + np * 16 + (lid & 7) + (lid >> 4) * 8;
                int kch = (k0 + ((lid >> 3) & 1) * 8) >> 3;
                uint32_t addr = Bb + row * 128 + (((kch ^ (row & 7))) << 4);
                uint32_t rr[4];
                ldmatrix_x4(rr, addr);
#pragma unroll
                for (int mi = 0; mi < 4; ++mi) {
                    mma16816h(acc[mi][np * 2],     a[mi], rr);
                    mma16816h(acc[mi][np * 2 + 1], a[mi], rr + 2);
                }
            }
        }
    };

    if (tid == 0) s_next = atomicAdd(&g_tile, 1);
    __syncthreads();
    int t = s_next;
    if (t < NTILE) {
        int rowBase, colBase; bool straddle;
        decode_tile(t, rowBase, colBase, straddle);
        load_stage(0, rowBase, colBase, 0);    // chunk 0 of first tile

        while (true) {
            __syncthreads();                    // all threads done reading s_next
            if (tid == 0) s_next = atomicAdd(&g_tile, 1);

#pragma unroll
            for (int mi = 0; mi < 4; ++mi)
#pragma unroll
                for (int nf = 0; nf < 8; ++nf) { acc[mi][nf][0] = 0u; acc[mi][nf][1] = 0u; }

            for (int c = 0; c < NCH - 1; ++c) {
                const int cur = c & 1;
                load_stage(cur ^ 1, rowBase, colBase, c + 1);
                asm volatile("cp.async.wait_group 1;");
                __syncthreads();
                compute_stage(cur);
                __syncthreads();
            }
            // chunk 7 (stage 1): prefetch next tile's chunk 0 into stage 0.
            int next_t = s_next;
            int nrowBase = 0, ncolBase = 0; bool nstraddle = false;
            if (next_t < NTILE) {
                decode_tile(next_t, nrowBase, ncolBase, nstraddle);
                load_stage(0, nrowBase, ncolBase, 0);
                asm volatile("cp.async.wait_group 1;");
            } else {
                asm volatile("cp.async.wait_group 0;");
            }
            __syncthreads();
            compute_stage(1);
            __syncthreads();

            // ---- epilogue (overlaps next tile's chunk-0 load) ----
            float rsum[4][2];
#pragma unroll
            for (int mi = 0; mi < 4; ++mi) { rsum[mi][0] = 0.f; rsum[mi][1] = 0.f; }
            float csum[8][2];
#pragma unroll
            for (int nf = 0; nf < 8; ++nf) { csum[nf][0] = 0.f; csum[nf][1] = 0.f; }

#pragma unroll
            for (int mi = 0; mi < 4; ++mi) {
                const int r0 = rowBase + wm * 64 + mi * 16 + (lid >> 2);
#pragma unroll
                for (int nf = 0; nf < 8; ++nf) {
                    const int c0 = colBase + wn * 64 + nf * 8 + (lid & 3) * 2;
                    float2 lo = __half22float2(*reinterpret_cast<__half2*>(&acc[mi][nf][0]));
                    float2 hi = __half22float2(*reinterpret_cast<__half2*>(&acc[mi][nf][1]));
                    float e0 = exp2dot(lo.x);
                    float e1 = exp2dot(lo.y);
                    float e2 = exp2dot(hi.x);
                    float e3 = exp2dot(hi.y);
                    if (straddle) {  // keep only strict lower triangle c < r
                        if (c0 >= r0)         e0 = 0.f;
                        if (c0 + 1 >= r0)     e1 = 0.f;
                        if (c0 >= r0 + 8)     e2 = 0.f;
                        if (c0 + 1 >= r0 + 8) e3 = 0.f;
                    }
                    rsum[mi][0] += e0 + e1;
                    rsum[mi][1] += e2 + e3;
                    csum[nf][0] += e0 + e2;
                    csum[nf][1] += e1 + e3;
                }
            }

#pragma unroll
            for (int mi = 0; mi < 4; ++mi)
#pragma unroll
                for (int rp = 0; rp < 2; ++rp) {
                    float v = rsum[mi][rp];
                    v += __shfl_xor_sync(0xffffffffu, v, 1);
                    v += __shfl_xor_sync(0xffffffffu, v, 2);
                    if ((lid & 3) == 0) {
                        int grow = rowBase + wm * 64 + mi * 16 + (lid >> 2) + rp * 8;
                        atomicAdd(&g_rowsum[grow], v);
                    }
                }

#pragma unroll
            for (int nf = 0; nf < 8; ++nf)
#pragma unroll
                for (int e = 0; e < 2; ++e) {
                    float v = csum[nf][e];
                    v += __shfl_xor_sync(0xffffffffu, v, 4);
                    v += __shfl_xor_sync(0xffffffffu, v, 8);
                    v += __shfl_xor_sync(0xffffffffu, v, 16);
                    if (lid < 4) {
                        int gcol = colBase + wn * 64 + nf * 8 + lid * 2 + e;
                        atomicAdd(&g_rowsum[gcol], v);
                    }
                }

            if (next_t >= NTILE) break;
            rowBase = nrowBase; colBase = ncolBase; straddle = nstraddle;
        }
    }

    // ================= Phase 3: finalize (last CTA) ========================
    __shared__ int s_rank;
    __threadfence();
    __syncthreads();
    if (tid == 0) s_rank = atomicAdd(&g_done, 1);
    __syncthreads();
    if (s_rank == G - 1) {
        float acc2 = 0.0f;
#pragma unroll
        for (int it = 0; it < N / 256; ++it) {
            int i = tid + it * 256;
            acc2 += __logf(__ldcg(&g_rowsum[i])) - __ldcg(&g_pos[i & (Bx - 1)]);
        }
#pragma unroll
        for (int o = 16; o > 0; o >>= 1)
            acc2 += __shfl_xor_sync(0xffffffffu, acc2, o);
        __shared__ float ws[8];
        if ((tid & 31) == 0) ws[tid >> 5] = acc2;
        __syncthreads();
        if (tid == 0) {
            float tot = 0.0f;
#pragma unroll
            for (int w = 0; w < 8; ++w) tot += ws[w];
            out[0] = tot / (float)N;
            // reset counters for the next graph replay
            g_tile = 0; g_prep_done = 0; g_done = 0;
        }
    }
}

extern "C" void kernel_launch(void* const* d_in, const int* in_sizes, int n_in,
                              void* d_out, int out_size) {
    const float* zis = (const float*)d_in[0];
    const float* zjs = (const float*)d_in[1];
    float* out = (float*)d_out;
    int dev = 0, sms = 0;
    cudaGetDevice(&dev);
    cudaDeviceGetAttribute(&sms, cudaDevAttrMultiProcessorCount, dev);
    const int G = 2 * sms;   // all CTAs resident (2/SM by smem+regs) => barrier safe
    cudaFuncSetAttribute(fused_kernel,
                         cudaFuncAttributeMaxDynamicSharedMemorySize, SMEM_TOTAL);
    fused_kernel<<<G, 256, SMEM_TOTAL>>>(zis, zjs, out, G);
}

// round 17
// speedup vs baseline: 1.0568x; 1.0568x over previous
#include <cuda_runtime.h>
#include <cuda_fp16.h>
#include <cstdint>

static constexpr int Bx = 4096;
static constexpr int D  = 512;
static constexpr int N  = 8192;
static constexpr float EPS = 1e-8f;

static constexpr int TM = 128;         // tile rows
static constexpr int TN = 256;         // tile cols
static constexpr int BK = 64;          // k-chunk: 64 fp16 = 128B rows
static constexpr int NCH = D / BK;     // 8
static constexpr int NTILE = 1056;     // sum_{I=0}^{63} (I/2 + 1)

static constexpr int STAGE_BYTES = (TM + TN) * BK * 2;   // 49152
static constexpr int SMEM_TOTAL  = 2 * STAGE_BYTES;      // 98304

// scratch (device globals — no allocation allowed)
__device__ __align__(256) __half g_Zh[(size_t)N * D];  // normalized fp16 reps
__device__ float g_pos[Bx];
__device__ float g_rowsum[N];

// ---------------------------------------------------------------------------
// Kernel 1: prep, ONE pair per warp (4096 warps -> higher occupancy).
//   reps row p      = zjs_p / ||zjs_p||       (fp16)
//   reps row Bx + p = zis_p / ||zis_p||       (fp16)
//   pos[p] = dot(zis_p, zjs_p)/(||zis_p|| ||zjs_p||) / TEMP   (exact fp32)
// Zeroes g_rowsum rows and out[0] (graph replays need fresh zeros).
// ---------------------------------------------------------------------------
__global__ void __launch_bounds__(256) prep_kernel(const float* __restrict__ zis,
                                                   const float* __restrict__ zjs,
                                                   float* __restrict__ out) {
    const int w   = (blockIdx.x * 256 + threadIdx.x) >> 5;  // pair index
    const int lid = threadIdx.x & 31;
    const float4* pa = reinterpret_cast<const float4*>(zis + (size_t)w * D);
    const float4* pb = reinterpret_cast<const float4*>(zjs + (size_t)w * D);

    float4 a[4], b[4];
#pragma unroll
    for (int q = 0; q < 4; ++q) a[q] = pa[q * 32 + lid];
#pragma unroll
    for (int q = 0; q < 4; ++q) b[q] = pb[q * 32 + lid];

    float sa = 0.f, sb = 0.f, dd = 0.f;
#pragma unroll
    for (int q = 0; q < 4; ++q) {
        sa = fmaf(a[q].x, a[q].x, fmaf(a[q].y, a[q].y,
             fmaf(a[q].z, a[q].z, fmaf(a[q].w, a[q].w, sa))));
        sb = fmaf(b[q].x, b[q].x, fmaf(b[q].y, b[q].y,
             fmaf(b[q].z, b[q].z, fmaf(b[q].w, b[q].w, sb))));
        dd = fmaf(a[q].x, b[q].x, fmaf(a[q].y, b[q].y,
             fmaf(a[q].z, b[q].z, fmaf(a[q].w, b[q].w, dd))));
    }
#pragma unroll
    for (int o = 16; o > 0; o >>= 1) {
        sa += __shfl_xor_sync(0xffffffffu, sa, o);
        sb += __shfl_xor_sync(0xffffffffu, sb, o);
        dd += __shfl_xor_sync(0xffffffffu, dd, o);
    }
    const float na = fmaxf(sqrtf(sa), EPS);
    const float nb = fmaxf(sqrtf(sb), EPS);
    if (lid == 0) {
        g_pos[w] = dd / (na * nb) * 2.0f;   // 1/TEMP = 2
        g_rowsum[w] = 0.0f;
        g_rowsum[Bx + w] = 0.0f;
        if (w == 0) out[0] = 0.0f;          // reset accumulator each replay
    }
    const float ia = 1.0f / na, ib = 1.0f / nb;

    uint2* rowJ = reinterpret_cast<uint2*>(&g_Zh[(size_t)w * D]);        // zjs row
    uint2* rowI = reinterpret_cast<uint2*>(&g_Zh[(size_t)(Bx + w) * D]); // zis row
#pragma unroll
    for (int q = 0; q < 4; ++q) {
        __half2 j0 = __floats2half2_rn(b[q].x * ib, b[q].y * ib);
        __half2 j1 = __floats2half2_rn(b[q].z * ib, b[q].w * ib);
        uint2 sj;
        sj.x = *reinterpret_cast<uint32_t*>(&j0);
        sj.y = *reinterpret_cast<uint32_t*>(&j1);
        rowJ[q * 32 + lid] = sj;
        __half2 i0 = __floats2half2_rn(a[q].x * ia, a[q].y * ia);
        __half2 i1 = __floats2half2_rn(a[q].z * ia, a[q].w * ia);
        uint2 si;
        si.x = *reinterpret_cast<uint32_t*>(&i0);
        si.y = *reinterpret_cast<uint32_t*>(&i1);
        rowI[q * 32 + lid] = si;
    }
}

// ---------------------------------------------------------------------------
// GEMM kernel: HMMA m16n8k16 f16-acc, 128x256 tile, strict-lower-triangle grid.
// 2-stage cp.async pipeline. Warp tile 64x64 (gm=2 x gn=4). (R13, proven.)
// Every kept element (c < r) contributes exp to rowsum[r] AND rowsum[c].
// ---------------------------------------------------------------------------
__device__ __forceinline__ void ldmatrix_x4(uint32_t* r, uint32_t addr) {
    asm volatile(
        "ldmatrix.sync.aligned.m8n8.x4.shared.b16 {%0, %1, %2, %3}, [%4];"
        : "=r"(r[0]), "=r"(r[1]), "=r"(r[2]), "=r"(r[3]) : "r"(addr));
}

__device__ __forceinline__ void mma16816h(uint32_t* d, const uint32_t* a,
                                          const uint32_t* b) {
    asm volatile(
        "mma.sync.aligned.m16n8k16.row.col.f16.f16.f16.f16 "
        "{%0, %1}, {%2, %3, %4, %5}, {%6, %7}, {%0, %1};"
        : "+r"(d[0]), "+r"(d[1])
        : "r"(a[0]), "r"(a[1]), "r"(a[2]), "r"(a[3]), "r"(b[0]), "r"(b[1]));
}

__device__ __forceinline__ float exp2dot(float dot) {
    // exp(2*dot) = (poly6(dot/4))^8, |dot/4| <= ~0.26 -> Taylor err ~1e-8
    float r = dot * 0.25f;
    float p = 1.0f / 720.0f;
    p = fmaf(p, r, 1.0f / 120.0f);
    p = fmaf(p, r, 1.0f / 24.0f);
    p = fmaf(p, r, 1.0f / 6.0f);
    p = fmaf(p, r, 0.5f);
    p = fmaf(p, r, 1.0f);
    p = fmaf(p, r, 1.0f);
    p = p * p; p = p * p; p = p * p;
    return p;
}

__global__ void __launch_bounds__(256, 2) gemm_kernel() {
    extern __shared__ __align__(1024) char dynsmem[];
    const uint32_t smem_base = (uint32_t)__cvta_generic_to_shared(dynsmem);
    const int tid = threadIdx.x;
    const int wid = tid >> 5, lid = tid & 31;
    const int wm = wid & 1;        // 2 warps along M (64 rows each)
    const int wn = wid >> 1;       // 4 warps along N (64 cols each)

    // tile decode: blocks (I, J), I in [0,64), J in [0, I/2].
    // cumulative starts: f(2m) = m^2 + m, f(2m+1) = (m+1)^2.
    int t = blockIdx.x;
    int s = (int)sqrtf((float)t);
    while ((s + 1) * (s + 1) <= t) ++s;
    while (s * s > t) --s;
    int I, J;
    if (t < s * s + s) { I = 2 * s - 1; J = t - s * s; }
    else               { I = 2 * s;     J = t - s * s - s; }
    const int rowBase = I * TM;
    const int colBase = J * TN;
    const bool straddle = (J == (I >> 1));  // tile contains c >= r elements

    uint32_t acc[4][8][2];   // f16x2 accumulators: 4 m-frags x 8 n-frags
#pragma unroll
    for (int mi = 0; mi < 4; ++mi)
#pragma unroll
        for (int nf = 0; nf < 8; ++nf) { acc[mi][nf][0] = 0u; acc[mi][nf][1] = 0u; }

    // cp.async tile loader: rows of 64 fp16 (128B = 8 x 16B chunks), xor swizzle
    auto load_stage = [&](int stage, int c) {
        const uint32_t Ab = smem_base + stage * STAGE_BYTES;
        const uint32_t Bb = Ab + TM * BK * 2;
        const int k0 = c * BK;
#pragma unroll
        for (int it = 0; it < 4; ++it) {       // A: 128 rows * 8 chunks
            int idx = tid + it * 256;
            int r = idx >> 3, seg = idx & 7;
            const __half* src = &g_Zh[(size_t)(rowBase + r) * D + k0 + seg * 8];
            uint32_t dst = Ab + r * 128 + ((seg ^ (r & 7)) << 4);
            asm volatile("cp.async.cg.shared.global [%0], [%1], 16;"
                         :: "r"(dst), "l"(src));
        }
#pragma unroll
        for (int it = 0; it < 8; ++it) {       // B: 256 rows * 8 chunks
            int idx = tid + it * 256;
            int r = idx >> 3, seg = idx & 7;
            const __half* src = &g_Zh[(size_t)(colBase + r) * D + k0 + seg * 8];
            uint32_t dst = Bb + r * 128 + ((seg ^ (r & 7)) << 4);
            asm volatile("cp.async.cg.shared.global [%0], [%1], 16;"
                         :: "r"(dst), "l"(src));
        }
        asm volatile("cp.async.commit_group;");
    };

    auto compute_stage = [&](int stage) {
        const uint32_t Ab = smem_base + stage * STAGE_BYTES;
        const uint32_t Bb = Ab + TM * BK * 2;
#pragma unroll
        for (int ks = 0; ks < 4; ++ks) {
            const int k0 = ks * 16;  // fp16 index
            uint32_t a[4][4];
#pragma unroll
            for (int mi = 0; mi < 4; ++mi) {
                int row = wm * 64 + mi * 16 + (lid & 7) + ((lid >> 3) & 1) * 8;
                int kch = (k0 + (lid >> 4) * 8) >> 3;
                uint32_t addr = Ab + row * 128 + (((kch ^ (row & 7))) << 4);
                ldmatrix_x4(a[mi], addr);
            }
#pragma unroll
            for (int np = 0; np < 4; ++np) {   // 4 x 16-col B fragments
                int row = wn * 64 + np * 16 + (lid & 7) + (lid >> 4) * 8;
                int kch = (k0 + ((lid >> 3) & 1) * 8) >> 3;
                uint32_t addr = Bb + row * 128 + (((kch ^ (row & 7))) << 4);
                uint32_t rr[4];
                ldmatrix_x4(rr, addr);
#pragma unroll
                for (int mi = 0; mi < 4; ++mi) {
                    mma16816h(acc[mi][np * 2],     a[mi], rr);
                    mma16816h(acc[mi][np * 2 + 1], a[mi], rr + 2);
                }
            }
        }
    };

    load_stage(0, 0);
    for (int c = 0; c < NCH; ++c) {
        const int cur = c & 1;
        if (c + 1 < NCH) load_stage(cur ^ 1, c + 1);
        if (c + 1 < NCH) asm volatile("cp.async.wait_group 1;");
        else             asm volatile("cp.async.wait_group 0;");
        __syncthreads();
        compute_stage(cur);
        __syncthreads();
    }

    // ---- epilogue: exp over strict-lower elements; row AND col sums ----
    float rsum[4][2];
#pragma unroll
    for (int mi = 0; mi < 4; ++mi) { rsum[mi][0] = 0.f; rsum[mi][1] = 0.f; }
    float csum[8][2];
#pragma unroll
    for (int nf = 0; nf < 8; ++nf) { csum[nf][0] = 0.f; csum[nf][1] = 0.f; }

#pragma unroll
    for (int mi = 0; mi < 4; ++mi) {
        const int r0 = rowBase + wm * 64 + mi * 16 + (lid >> 2);
#pragma unroll
        for (int nf = 0; nf < 8; ++nf) {
            const int c0 = colBase + wn * 64 + nf * 8 + (lid & 3) * 2;
            float2 lo = __half22float2(*reinterpret_cast<__half2*>(&acc[mi][nf][0]));
            float2 hi = __half22float2(*reinterpret_cast<__half2*>(&acc[mi][nf][1]));
            float e0 = exp2dot(lo.x);
            float e1 = exp2dot(lo.y);
            float e2 = exp2dot(hi.x);
            float e3 = exp2dot(hi.y);
            if (straddle) {  // keep only strict lower triangle c < r
                if (c0 >= r0)         e0 = 0.f;
                if (c0 + 1 >= r0)     e1 = 0.f;
                if (c0 >= r0 + 8)     e2 = 0.f;
                if (c0 + 1 >= r0 + 8) e3 = 0.f;
            }
            rsum[mi][0] += e0 + e1;
            rsum[mi][1] += e2 + e3;
            csum[nf][0] += e0 + e2;
            csum[nf][1] += e1 + e3;
        }
    }

    // row sums: reduce over lanes sharing a row (lid&3), lane%4==0 commits
#pragma unroll
    for (int mi = 0; mi < 4; ++mi)
#pragma unroll
        for (int rp = 0; rp < 2; ++rp) {
            float v = rsum[mi][rp];
            v += __shfl_xor_sync(0xffffffffu, v, 1);
            v += __shfl_xor_sync(0xffffffffu, v, 2);
            if ((lid & 3) == 0) {
                int grow = rowBase + wm * 64 + mi * 16 + (lid >> 2) + rp * 8;
                atomicAdd(&g_rowsum[grow], v);
            }
        }

    // col sums (transpose contributions) — every tile
#pragma unroll
    for (int nf = 0; nf < 8; ++nf)
#pragma unroll
        for (int e = 0; e < 2; ++e) {
            float v = csum[nf][e];
            v += __shfl_xor_sync(0xffffffffu, v, 4);
            v += __shfl_xor_sync(0xffffffffu, v, 8);
            v += __shfl_xor_sync(0xffffffffu, v, 16);
            if (lid < 4) {
                int gcol = colBase + wn * 64 + nf * 8 + lid * 2 + e;
                atomicAdd(&g_rowsum[gcol], v);
            }
        }
}

// ---------------------------------------------------------------------------
// finalize: 16 blocks x 512 threads; block partials atomicAdd'ed into out[0].
// out[0] is zeroed by prep each launch/replay.
// ---------------------------------------------------------------------------
__global__ void __launch_bounds__(512) finalize_kernel(float* __restrict__ out) {
    const int tid = threadIdx.x;
    const int i = blockIdx.x * 512 + tid;
    float acc = __logf(g_rowsum[i]) - g_pos[i & (Bx - 1)];
#pragma unroll
    for (int o = 16; o > 0; o >>= 1) acc += __shfl_xor_sync(0xffffffffu, acc, o);
    __shared__ float ws[16];
    if ((tid & 31) == 0) ws[tid >> 5] = acc;
    __syncthreads();
    if (tid < 32) {
        float v = (tid < 16) ? ws[tid] : 0.0f;
#pragma unroll
        for (int o = 8; o > 0; o >>= 1) v += __shfl_xor_sync(0xffffffffu, v, o);
        if (tid == 0) atomicAdd(out, v * (1.0f / (float)N));
    }
}

extern "C" void kernel_launch(void* const* d_in, const int* in_sizes, int n_in,
                              void* d_out, int out_size) {
    const float* zis = (const float*)d_in[0];
    const float* zjs = (const float*)d_in[1];
    float* out = (float*)d_out;
    cudaFuncSetAttribute(gemm_kernel,
                         cudaFuncAttributeMaxDynamicSharedMemorySize, SMEM_TOTAL);
    prep_kernel<<<Bx / 8, 256>>>(zis, zjs, out);
    gemm_kernel<<<NTILE, 256, SMEM_TOTAL>>>();
    finalize_kernel<<<N / 512, 512>>>(out);
}